// round 2
// baseline (speedup 1.0000x reference)
#include <cuda_runtime.h>
#include <cstdint>

// ---------------- problem constants (fixed by setup_inputs) ----------------
#define MAXN 50000
#define MAXE 800000
#define FN   92
#define FE   64
#define HDIM 128
#define NGR  256

// ---------------- scratch (device globals; no allocations) ----------------
__device__ float g_h   [MAXN * HDIM];   // node features
__device__ float g_sh  [MAXN * HDIM];   // S*h  (neighbor-sum of h)
__device__ float g_ea  [MAXN * FE];     // S*edge_attr (layer-invariant)
__device__ float g_dinv[MAXN];          // 1/max(deg,1)
__device__ int   g_cnt [MAXN];
__device__ int   g_rowptr[MAXN + 1];
__device__ int   g_rowfill[MAXN];
__device__ int   g_cols[MAXE];          // source node per CSR slot
__device__ int   g_eids[MAXE];          // edge id per CSR slot
__device__ float g_pool[NGR * HDIM];

// ---------------- CSR build ----------------
__global__ void k_zero(int N) {
    int i = blockIdx.x * blockDim.x + threadIdx.x;
    if (i < N) g_cnt[i] = 0;
}

__global__ void k_hist(const int* __restrict__ row, int E) {
    int e = blockIdx.x * blockDim.x + threadIdx.x;
    if (e < E) atomicAdd(&g_cnt[row[e]], 1);
}

__global__ void k_scan(int N) {
    __shared__ int ssum[1024];
    int t = threadIdx.x;
    int per = (N + 1023) / 1024;
    int s0 = t * per; if (s0 > N) s0 = N;
    int s1 = s0 + per; if (s1 > N) s1 = N;
    int local = 0;
    for (int i = s0; i < s1; i++) local += g_cnt[i];
    ssum[t] = local;
    __syncthreads();
    for (int off = 1; off < 1024; off <<= 1) {
        int v = 0;
        if (t >= off) v = ssum[t - off];
        __syncthreads();
        ssum[t] += v;
        __syncthreads();
    }
    int run = ssum[t] - local;   // exclusive prefix
    for (int i = s0; i < s1; i++) {
        g_rowptr[i] = run;
        g_rowfill[i] = run;
        int c = g_cnt[i];
        g_dinv[i] = 1.0f / (c > 0 ? (float)c : 1.0f);
        run += c;
    }
    if (t == 1023) g_rowptr[N] = ssum[1023];
}

__global__ void k_scatter(const int* __restrict__ row, const int* __restrict__ col, int E) {
    int e = blockIdx.x * blockDim.x + threadIdx.x;
    if (e < E) {
        int r = row[e];
        int pos = atomicAdd(&g_rowfill[r], 1);
        g_cols[pos] = col[e];
        g_eids[pos] = e;
    }
}

// ---------------- embedding GEMM: h = relu(x @ W_emb + b) ----------------
// BM=128, BN=128, BK=16, 256 threads, 8x8 per thread, A transposed in smem.
__global__ __launch_bounds__(256) void k_embed(
    const float* __restrict__ x, const float* __restrict__ W,
    const float* __restrict__ b, int N)
{
    __shared__ float As[16][HDIM];
    __shared__ float Bs[16][HDIM];
    int t = threadIdx.x;
    int m0 = blockIdx.x * 128;
    int tx = t & 15;   // col group: cols tx*8..+7
    int ty = t >> 4;   // row group: rows ty*8..+7
    float acc[8][8];
#pragma unroll
    for (int r = 0; r < 8; r++)
#pragma unroll
        for (int c = 0; c < 8; c++) acc[r][c] = 0.f;

    for (int k0 = 0; k0 < FN; k0 += 16) {
        // A tile: 128 rows x 16 k = 512 float4, transposed store
#pragma unroll
        for (int i = 0; i < 2; i++) {
            int f4 = t + i * 256;
            int rowi = f4 >> 2;         // 0..127
            int kq = (f4 & 3) * 4;      // 0,4,8,12
            int gm = m0 + rowi, gk = k0 + kq;
            float4 v = make_float4(0.f, 0.f, 0.f, 0.f);
            if (gm < N && gk < FN) v = *(const float4*)&x[(size_t)gm * FN + gk];
            As[kq + 0][rowi] = v.x;
            As[kq + 1][rowi] = v.y;
            As[kq + 2][rowi] = v.z;
            As[kq + 3][rowi] = v.w;
        }
        // B tile: 16 k x 128 cols = 512 float4
#pragma unroll
        for (int i = 0; i < 2; i++) {
            int f4 = t + i * 256;
            int kk = f4 >> 5;           // 0..15
            int nq = (f4 & 31) * 4;
            int gk = k0 + kk;
            float4 v = make_float4(0.f, 0.f, 0.f, 0.f);
            if (gk < FN) v = *(const float4*)&W[(size_t)gk * HDIM + nq];
            *(float4*)&Bs[kk][nq] = v;
        }
        __syncthreads();
#pragma unroll
        for (int kk = 0; kk < 16; kk++) {
            float4 a0 = *(float4*)&As[kk][ty * 8];
            float4 a1 = *(float4*)&As[kk][ty * 8 + 4];
            float4 b0 = *(float4*)&Bs[kk][tx * 8];
            float4 b1 = *(float4*)&Bs[kk][tx * 8 + 4];
            float av[8] = {a0.x, a0.y, a0.z, a0.w, a1.x, a1.y, a1.z, a1.w};
            float bv[8] = {b0.x, b0.y, b0.z, b0.w, b1.x, b1.y, b1.z, b1.w};
#pragma unroll
            for (int r = 0; r < 8; r++)
#pragma unroll
                for (int c = 0; c < 8; c++)
                    acc[r][c] = fmaf(av[r], bv[c], acc[r][c]);
        }
        __syncthreads();
    }
    float4 bb0 = *(const float4*)&b[tx * 8];
    float4 bb1 = *(const float4*)&b[tx * 8 + 4];
    float bv[8] = {bb0.x, bb0.y, bb0.z, bb0.w, bb1.x, bb1.y, bb1.z, bb1.w};
#pragma unroll
    for (int r = 0; r < 8; r++) {
        int gm = m0 + ty * 8 + r;
        if (gm < N) {
            float4 o0, o1;
            o0.x = fmaxf(acc[r][0] + bv[0], 0.f);
            o0.y = fmaxf(acc[r][1] + bv[1], 0.f);
            o0.z = fmaxf(acc[r][2] + bv[2], 0.f);
            o0.w = fmaxf(acc[r][3] + bv[3], 0.f);
            o1.x = fmaxf(acc[r][4] + bv[4], 0.f);
            o1.y = fmaxf(acc[r][5] + bv[5], 0.f);
            o1.z = fmaxf(acc[r][6] + bv[6], 0.f);
            o1.w = fmaxf(acc[r][7] + bv[7], 0.f);
            *(float4*)&g_h[(size_t)gm * HDIM + tx * 8] = o0;
            *(float4*)&g_h[(size_t)gm * HDIM + tx * 8 + 4] = o1;
        }
    }
}

// ---------------- EA aggregation (once): g_ea[i] = sum_in-edges edge_attr[e] ----------------
__global__ __launch_bounds__(256) void k_ea_agg(const float* __restrict__ ea, int N) {
    int w = (blockIdx.x * blockDim.x + threadIdx.x) >> 5;
    int lane = threadIdx.x & 31;
    if (w >= N) return;
    int s = g_rowptr[w], e = g_rowptr[w + 1];
    float2 a0 = make_float2(0.f, 0.f), a1 = make_float2(0.f, 0.f);
    float2 a2 = make_float2(0.f, 0.f), a3 = make_float2(0.f, 0.f);
    int i = s;
    for (; i + 3 < e; i += 4) {
        int i0 = g_eids[i], i1 = g_eids[i+1], i2 = g_eids[i+2], i3 = g_eids[i+3];
        float2 v0 = *(const float2*)&ea[(size_t)i0 * FE + lane * 2];
        float2 v1 = *(const float2*)&ea[(size_t)i1 * FE + lane * 2];
        float2 v2 = *(const float2*)&ea[(size_t)i2 * FE + lane * 2];
        float2 v3 = *(const float2*)&ea[(size_t)i3 * FE + lane * 2];
        a0.x += v0.x; a0.y += v0.y;
        a1.x += v1.x; a1.y += v1.y;
        a2.x += v2.x; a2.y += v2.y;
        a3.x += v3.x; a3.y += v3.y;
    }
    for (; i < e; i++) {
        int id = g_eids[i];
        float2 v = *(const float2*)&ea[(size_t)id * FE + lane * 2];
        a0.x += v.x; a0.y += v.y;
    }
    float2 r;
    r.x = (a0.x + a1.x) + (a2.x + a3.x);
    r.y = (a0.y + a1.y) + (a2.y + a3.y);
    *(float2*)&g_ea[(size_t)w * FE + lane * 2] = r;
}

// ---------------- per-layer neighbor-sum: g_sh[i] = sum h[col] over in-edges ----------------
__global__ __launch_bounds__(256) void k_sh_agg(int N) {
    int w = (blockIdx.x * blockDim.x + threadIdx.x) >> 5;
    int lane = threadIdx.x & 31;
    if (w >= N) return;
    int s = g_rowptr[w], e = g_rowptr[w + 1];
    float4 a0 = make_float4(0.f,0.f,0.f,0.f), a1 = a0, a2 = a0, a3 = a0;
    int i = s;
    for (; i + 3 < e; i += 4) {
        int c0 = g_cols[i], c1 = g_cols[i+1], c2 = g_cols[i+2], c3 = g_cols[i+3];
        float4 v0 = *(const float4*)&g_h[(size_t)c0 * HDIM + lane * 4];
        float4 v1 = *(const float4*)&g_h[(size_t)c1 * HDIM + lane * 4];
        float4 v2 = *(const float4*)&g_h[(size_t)c2 * HDIM + lane * 4];
        float4 v3 = *(const float4*)&g_h[(size_t)c3 * HDIM + lane * 4];
        a0.x+=v0.x; a0.y+=v0.y; a0.z+=v0.z; a0.w+=v0.w;
        a1.x+=v1.x; a1.y+=v1.y; a1.z+=v1.z; a1.w+=v1.w;
        a2.x+=v2.x; a2.y+=v2.y; a2.z+=v2.z; a2.w+=v2.w;
        a3.x+=v3.x; a3.y+=v3.y; a3.z+=v3.z; a3.w+=v3.w;
    }
    for (; i < e; i++) {
        int c = g_cols[i];
        float4 v = *(const float4*)&g_h[(size_t)c * HDIM + lane * 4];
        a0.x+=v.x; a0.y+=v.y; a0.z+=v.z; a0.w+=v.w;
    }
    float4 r;
    r.x = (a0.x + a1.x) + (a2.x + a3.x);
    r.y = (a0.y + a1.y) + (a2.y + a3.y);
    r.z = (a0.z + a1.z) + (a2.z + a3.z);
    r.w = (a0.w + a1.w) + (a2.w + a3.w);
    *(float4*)&g_sh[(size_t)w * HDIM + lane * 4] = r;
}

// ---------------- layer GEMM + fused epilogue ----------------
// h += relu(((Sh @ Wl[0:128] + EA @ Wl[128:192]) * dinv + bc) * gamma/sqrt(1+eps) + beta)
__global__ __launch_bounds__(256) void k_layer(
    const float* __restrict__ Wl, const float* __restrict__ bcl,
    const float* __restrict__ gml, const float* __restrict__ bel, int N)
{
    __shared__ float As[16][HDIM];
    __shared__ float Bs[16][HDIM];
    const float RS = rsqrtf(1.001f);   // 1/sqrt(1 + 1e-3)
    int t = threadIdx.x;
    int m0 = blockIdx.x * 128;
    int tx = t & 15;
    int ty = t >> 4;
    float acc[8][8];
#pragma unroll
    for (int r = 0; r < 8; r++)
#pragma unroll
        for (int c = 0; c < 8; c++) acc[r][c] = 0.f;

    for (int kt = 0; kt < 12; kt++) {          // K = 192 = 12 * 16
        int k0 = kt * 16;
#pragma unroll
        for (int i = 0; i < 2; i++) {
            int f4 = t + i * 256;
            int rowi = f4 >> 2;
            int kq = (f4 & 3) * 4;
            int gm = m0 + rowi;
            int gk = k0 + kq;
            float4 v = make_float4(0.f, 0.f, 0.f, 0.f);
            if (gm < N) {
                if (gk < HDIM) v = *(const float4*)&g_sh[(size_t)gm * HDIM + gk];
                else           v = *(const float4*)&g_ea[(size_t)gm * FE + (gk - HDIM)];
            }
            As[kq + 0][rowi] = v.x;
            As[kq + 1][rowi] = v.y;
            As[kq + 2][rowi] = v.z;
            As[kq + 3][rowi] = v.w;
        }
#pragma unroll
        for (int i = 0; i < 2; i++) {
            int f4 = t + i * 256;
            int kk = f4 >> 5;
            int nq = (f4 & 31) * 4;
            float4 v = *(const float4*)&Wl[(size_t)(k0 + kk) * HDIM + nq];
            *(float4*)&Bs[kk][nq] = v;
        }
        __syncthreads();
#pragma unroll
        for (int kk = 0; kk < 16; kk++) {
            float4 a0 = *(float4*)&As[kk][ty * 8];
            float4 a1 = *(float4*)&As[kk][ty * 8 + 4];
            float4 b0 = *(float4*)&Bs[kk][tx * 8];
            float4 b1 = *(float4*)&Bs[kk][tx * 8 + 4];
            float av[8] = {a0.x, a0.y, a0.z, a0.w, a1.x, a1.y, a1.z, a1.w};
            float bv[8] = {b0.x, b0.y, b0.z, b0.w, b1.x, b1.y, b1.z, b1.w};
#pragma unroll
            for (int r = 0; r < 8; r++)
#pragma unroll
                for (int c = 0; c < 8; c++)
                    acc[r][c] = fmaf(av[r], bv[c], acc[r][c]);
        }
        __syncthreads();
    }
    int n0 = tx * 8;
    float4 bc0 = *(const float4*)&bcl[n0], bc1 = *(const float4*)&bcl[n0 + 4];
    float4 gm0 = *(const float4*)&gml[n0], gm1 = *(const float4*)&gml[n0 + 4];
    float4 be0 = *(const float4*)&bel[n0], be1 = *(const float4*)&bel[n0 + 4];
    float bcv[8] = {bc0.x, bc0.y, bc0.z, bc0.w, bc1.x, bc1.y, bc1.z, bc1.w};
    float csv[8] = {gm0.x * RS, gm0.y * RS, gm0.z * RS, gm0.w * RS,
                    gm1.x * RS, gm1.y * RS, gm1.z * RS, gm1.w * RS};
    float bev[8] = {be0.x, be0.y, be0.z, be0.w, be1.x, be1.y, be1.z, be1.w};
#pragma unroll
    for (int r = 0; r < 8; r++) {
        int gm = m0 + ty * 8 + r;
        if (gm < N) {
            float dinv = g_dinv[gm];
            float4 old0 = *(float4*)&g_h[(size_t)gm * HDIM + n0];
            float4 old1 = *(float4*)&g_h[(size_t)gm * HDIM + n0 + 4];
            float oldv[8] = {old0.x, old0.y, old0.z, old0.w, old1.x, old1.y, old1.z, old1.w};
            float ov[8];
#pragma unroll
            for (int c = 0; c < 8; c++) {
                float v = fmaf(fmaf(acc[r][c], dinv, bcv[c]), csv[c], bev[c]);
                ov[c] = oldv[c] + fmaxf(v, 0.f);
            }
            float4 o0 = {ov[0], ov[1], ov[2], ov[3]};
            float4 o1 = {ov[4], ov[5], ov[6], ov[7]};
            *(float4*)&g_h[(size_t)gm * HDIM + n0] = o0;
            *(float4*)&g_h[(size_t)gm * HDIM + n0 + 4] = o1;
        }
    }
}

// ---------------- mean pooling per graph (batch_idx sorted) ----------------
__device__ __forceinline__ int lb_search(const int* a, int n, int v) {
    int lo = 0, hi = n;
    while (lo < hi) { int m = (lo + hi) >> 1; if (a[m] < v) lo = m + 1; else hi = m; }
    return lo;
}

__global__ void k_pool(const int* __restrict__ batch, int N) {
    int gid = blockIdx.x;
    int t = threadIdx.x;   // 128 threads = columns
    int lo = lb_search(batch, N, gid);
    int hi = lb_search(batch, N, gid + 1);
    float s = 0.f;
    for (int i = lo; i < hi; i++) s += g_h[(size_t)i * HDIM + t];
    int c = hi - lo;
    g_pool[gid * HDIM + t] = s / (c > 0 ? (float)c : 1.0f);
}

// ---------------- head: out = relu(g @ Wh + bh) @ Wout + bout ----------------
__global__ void k_head(const float* __restrict__ Wh, const float* __restrict__ bh,
                       const float* __restrict__ Wout, const float* __restrict__ bout,
                       float* __restrict__ out)
{
    __shared__ float grow[HDIM];
    __shared__ float red[HDIM];
    int gid = blockIdx.x;
    int t = threadIdx.x;
    grow[t] = g_pool[gid * HDIM + t];
    __syncthreads();
    float s = bh[t];
#pragma unroll 8
    for (int k = 0; k < HDIM; k++) s = fmaf(grow[k], Wh[k * HDIM + t], s);
    s = fmaxf(s, 0.f);
    red[t] = s * Wout[t];
    __syncthreads();
    for (int off = 64; off > 0; off >>= 1) {
        if (t < off) red[t] += red[t + off];
        __syncthreads();
    }
    if (t == 0) out[gid] = red[0] + bout[0];
}

// ---------------- launch ----------------
extern "C" void kernel_launch(void* const* d_in, const int* in_sizes, int n_in,
                              void* d_out, int out_size)
{
    const float* x      = (const float*)d_in[0];
    const int*   ei     = (const int*)  d_in[1];
    const float* eattr  = (const float*)d_in[2];
    const int*   batch  = (const int*)  d_in[3];
    const float* W_emb  = (const float*)d_in[4];
    const float* b_emb  = (const float*)d_in[5];
    const float* Wc     = (const float*)d_in[6];
    const float* bc     = (const float*)d_in[7];
    const float* gamma  = (const float*)d_in[8];
    const float* beta   = (const float*)d_in[9];
    const float* Wh     = (const float*)d_in[10];
    const float* bh     = (const float*)d_in[11];
    const float* Wout   = (const float*)d_in[12];
    const float* bout   = (const float*)d_in[13];

    int N = in_sizes[3];
    int E = in_sizes[2] / FE;
    int L = in_sizes[6] / ((HDIM + FE) * HDIM);
    int G = out_size;
    const int* row = ei;
    const int* col = ei + E;

    k_zero<<<(N + 255) / 256, 256>>>(N);
    k_hist<<<(E + 255) / 256, 256>>>(row, E);
    k_scan<<<1, 1024>>>(N);
    k_scatter<<<(E + 255) / 256, 256>>>(row, col, E);

    k_embed<<<(N + 127) / 128, 256>>>(x, W_emb, b_emb, N);
    k_ea_agg<<<(N * 32 + 255) / 256, 256>>>(eattr, N);

    for (int l = 0; l < L; l++) {
        k_sh_agg<<<(N * 32 + 255) / 256, 256>>>(N);
        k_layer<<<(N + 127) / 128, 256>>>(
            Wc + (size_t)l * (HDIM + FE) * HDIM,
            bc + (size_t)l * HDIM,
            gamma + (size_t)l * HDIM,
            beta + (size_t)l * HDIM, N);
    }

    k_pool<<<G, HDIM>>>(batch, N);
    k_head<<<G, HDIM>>>(Wh, bh, Wout, bout, (float*)d_out);
}

// round 6
// speedup vs baseline: 1.2953x; 1.2953x over previous
#include <cuda_runtime.h>
#include <cuda_bf16.h>
#include <cstdint>

// ---------------- problem constants ----------------
#define MAXN 50000
#define MAXE 800000
#define FN   92
#define FE   64
#define HDIM 128
#define NGR  256
#define MAXL 3

// ---------------- scratch ----------------
__device__ float g_h   [MAXN * HDIM];
__device__ float g_sh  [MAXN * HDIM];
__device__ float g_ea  [MAXN * FE];
__device__ float g_dinv[MAXN];
__device__ int   g_cnt [MAXN];
__device__ int   g_rowptr[MAXN + 1];
__device__ int   g_rowfill[MAXN];
__device__ int   g_cols[MAXE];
__device__ int   g_eids[MAXE];
__device__ float g_pool[NGR * HDIM];
// pre-transposed hi/lo-split weights: per layer [n=128][k=192] bf16 = 49152 B = 3072 uint4
__device__ uint4 g_Bhi[MAXL * 3072];
__device__ uint4 g_Blo[MAXL * 3072];

// ---------------- helpers ----------------
__device__ __forceinline__ uint32_t smem_u32(const void* p) {
    uint32_t a;
    asm("{ .reg .u64 t; cvta.to.shared.u64 t, %1; cvt.u32.u64 %0, t; }" : "=r"(a) : "l"(p));
    return a;
}

#define LDSM_X4(r, addr) \
    asm volatile("ldmatrix.sync.aligned.m8n8.x4.shared.b16 {%0,%1,%2,%3}, [%4];" \
        : "=r"((r)[0]), "=r"((r)[1]), "=r"((r)[2]), "=r"((r)[3]) : "r"(addr))

#define MMA_BF16(d, a, b) \
    asm volatile("mma.sync.aligned.m16n8k16.row.col.f32.bf16.bf16.f32 " \
        "{%0,%1,%2,%3}, {%4,%5,%6,%7}, {%8,%9}, {%0,%1,%2,%3};" \
        : "+f"((d)[0]), "+f"((d)[1]), "+f"((d)[2]), "+f"((d)[3]) \
        : "r"((a)[0]), "r"((a)[1]), "r"((a)[2]), "r"((a)[3]), "r"((b)[0]), "r"((b)[1]))

__device__ __forceinline__ uint32_t pack_hi2(float x, float y, float& rx, float& ry) {
    __nv_bfloat16 hx = __float2bfloat16_rn(x), hy = __float2bfloat16_rn(y);
    rx = x - __bfloat162float(hx);
    ry = y - __bfloat162float(hy);
    return (uint32_t)__bfloat16_as_ushort(hx) | ((uint32_t)__bfloat16_as_ushort(hy) << 16);
}
__device__ __forceinline__ uint32_t pack_lo2(float rx, float ry) {
    __nv_bfloat16 lx = __float2bfloat16_rn(rx), ly = __float2bfloat16_rn(ry);
    return (uint32_t)__bfloat16_as_ushort(lx) | ((uint32_t)__bfloat16_as_ushort(ly) << 16);
}

// ---------------- CSR build ----------------
__global__ void k_zero(int N) {
    int i = blockIdx.x * blockDim.x + threadIdx.x;
    if (i < N) g_cnt[i] = 0;
}
__global__ void k_hist(const int* __restrict__ row, int E) {
    int e = blockIdx.x * blockDim.x + threadIdx.x;
    if (e < E) atomicAdd(&g_cnt[row[e]], 1);
}
__global__ void k_scan(int N) {
    __shared__ int ssum[1024];
    int t = threadIdx.x;
    int per = (N + 1023) / 1024;
    int s0 = t * per; if (s0 > N) s0 = N;
    int s1 = s0 + per; if (s1 > N) s1 = N;
    int local = 0;
    for (int i = s0; i < s1; i++) local += g_cnt[i];
    ssum[t] = local;
    __syncthreads();
    for (int off = 1; off < 1024; off <<= 1) {
        int v = 0;
        if (t >= off) v = ssum[t - off];
        __syncthreads();
        ssum[t] += v;
        __syncthreads();
    }
    int run = ssum[t] - local;
    for (int i = s0; i < s1; i++) {
        g_rowptr[i] = run;
        g_rowfill[i] = run;
        int c = g_cnt[i];
        g_dinv[i] = 1.0f / (c > 0 ? (float)c : 1.0f);
        run += c;
    }
    if (t == 1023) g_rowptr[N] = ssum[1023];
}
__global__ void k_scatter(const int* __restrict__ row, const int* __restrict__ col, int E) {
    int e = blockIdx.x * blockDim.x + threadIdx.x;
    if (e < E) {
        int r = row[e];
        int pos = atomicAdd(&g_rowfill[r], 1);
        g_cols[pos] = col[e];
        g_eids[pos] = e;
    }
}

// ---------------- weight prep: transpose + hi/lo split ----------------
// Wc[l] is [192, 128] (k-major rows); store B as [n=128][k=192] bf16 hi & lo.
__global__ void k_prepB(const float* __restrict__ Wc, int L) {
    int i = blockIdx.x * blockDim.x + threadIdx.x;
    int total = L * 192 * 128;
    if (i >= total) return;
    int l = i / 24576;
    int rem = i - l * 24576;
    int k = rem >> 7;          // 0..191
    int n = rem & 127;         // 0..127  (coalesced read over n)
    float v = Wc[(size_t)l * 24576 + k * 128 + n];
    __nv_bfloat16 hi = __float2bfloat16_rn(v);
    float res = v - __bfloat162float(hi);
    __nv_bfloat16 lo = __float2bfloat16_rn(res);
    size_t off = (size_t)l * 24576 + n * 192 + k;
    ((__nv_bfloat16*)g_Bhi)[off] = hi;
    ((__nv_bfloat16*)g_Blo)[off] = lo;
}

// ---------------- embedding GEMM (fp32 SIMT): h = relu(x @ W_emb + b) ----------------
__global__ __launch_bounds__(256) void k_embed(
    const float* __restrict__ x, const float* __restrict__ W,
    const float* __restrict__ b, int N)
{
    __shared__ float As[16][HDIM];
    __shared__ float Bs[16][HDIM];
    int t = threadIdx.x;
    int m0 = blockIdx.x * 128;
    int tx = t & 15;
    int ty = t >> 4;
    float acc[8][8];
#pragma unroll
    for (int r = 0; r < 8; r++)
#pragma unroll
        for (int c = 0; c < 8; c++) acc[r][c] = 0.f;

    for (int k0 = 0; k0 < FN; k0 += 16) {
#pragma unroll
        for (int i = 0; i < 2; i++) {
            int f4 = t + i * 256;
            int rowi = f4 >> 2;
            int kq = (f4 & 3) * 4;
            int gm = m0 + rowi, gk = k0 + kq;
            float4 v = make_float4(0.f, 0.f, 0.f, 0.f);
            if (gm < N && gk < FN) v = *(const float4*)&x[(size_t)gm * FN + gk];
            As[kq + 0][rowi] = v.x;
            As[kq + 1][rowi] = v.y;
            As[kq + 2][rowi] = v.z;
            As[kq + 3][rowi] = v.w;
        }
#pragma unroll
        for (int i = 0; i < 2; i++) {
            int f4 = t + i * 256;
            int kk = f4 >> 5;
            int nq = (f4 & 31) * 4;
            int gk = k0 + kk;
            float4 v = make_float4(0.f, 0.f, 0.f, 0.f);
            if (gk < FN) v = *(const float4*)&W[(size_t)gk * HDIM + nq];
            *(float4*)&Bs[kk][nq] = v;
        }
        __syncthreads();
#pragma unroll
        for (int kk = 0; kk < 16; kk++) {
            float4 a0 = *(float4*)&As[kk][ty * 8];
            float4 a1 = *(float4*)&As[kk][ty * 8 + 4];
            float4 b0 = *(float4*)&Bs[kk][tx * 8];
            float4 b1 = *(float4*)&Bs[kk][tx * 8 + 4];
            float av[8] = {a0.x, a0.y, a0.z, a0.w, a1.x, a1.y, a1.z, a1.w};
            float bv[8] = {b0.x, b0.y, b0.z, b0.w, b1.x, b1.y, b1.z, b1.w};
#pragma unroll
            for (int r = 0; r < 8; r++)
#pragma unroll
                for (int c = 0; c < 8; c++)
                    acc[r][c] = fmaf(av[r], bv[c], acc[r][c]);
        }
        __syncthreads();
    }
    float4 bb0 = *(const float4*)&b[tx * 8];
    float4 bb1 = *(const float4*)&b[tx * 8 + 4];
    float bv[8] = {bb0.x, bb0.y, bb0.z, bb0.w, bb1.x, bb1.y, bb1.z, bb1.w};
#pragma unroll
    for (int r = 0; r < 8; r++) {
        int gm = m0 + ty * 8 + r;
        if (gm < N) {
            float4 o0, o1;
            o0.x = fmaxf(acc[r][0] + bv[0], 0.f);
            o0.y = fmaxf(acc[r][1] + bv[1], 0.f);
            o0.z = fmaxf(acc[r][2] + bv[2], 0.f);
            o0.w = fmaxf(acc[r][3] + bv[3], 0.f);
            o1.x = fmaxf(acc[r][4] + bv[4], 0.f);
            o1.y = fmaxf(acc[r][5] + bv[5], 0.f);
            o1.z = fmaxf(acc[r][6] + bv[6], 0.f);
            o1.w = fmaxf(acc[r][7] + bv[7], 0.f);
            *(float4*)&g_h[(size_t)gm * HDIM + tx * 8] = o0;
            *(float4*)&g_h[(size_t)gm * HDIM + tx * 8 + 4] = o1;
        }
    }
}

// ---------------- EA aggregation (once) ----------------
__global__ __launch_bounds__(256) void k_ea_agg(const float* __restrict__ ea, int N) {
    int w = (blockIdx.x * blockDim.x + threadIdx.x) >> 5;
    int lane = threadIdx.x & 31;
    if (w >= N) return;
    int s = g_rowptr[w], e = g_rowptr[w + 1];
    float2 a0 = make_float2(0.f, 0.f), a1 = a0, a2 = a0, a3 = a0;
    int i = s;
    for (; i + 3 < e; i += 4) {
        int i0 = g_eids[i], i1 = g_eids[i+1], i2 = g_eids[i+2], i3 = g_eids[i+3];
        float2 v0 = *(const float2*)&ea[(size_t)i0 * FE + lane * 2];
        float2 v1 = *(const float2*)&ea[(size_t)i1 * FE + lane * 2];
        float2 v2 = *(const float2*)&ea[(size_t)i2 * FE + lane * 2];
        float2 v3 = *(const float2*)&ea[(size_t)i3 * FE + lane * 2];
        a0.x += v0.x; a0.y += v0.y;
        a1.x += v1.x; a1.y += v1.y;
        a2.x += v2.x; a2.y += v2.y;
        a3.x += v3.x; a3.y += v3.y;
    }
    for (; i < e; i++) {
        int id = g_eids[i];
        float2 v = *(const float2*)&ea[(size_t)id * FE + lane * 2];
        a0.x += v.x; a0.y += v.y;
    }
    float2 r;
    r.x = (a0.x + a1.x) + (a2.x + a3.x);
    r.y = (a0.y + a1.y) + (a2.y + a3.y);
    *(float2*)&g_ea[(size_t)w * FE + lane * 2] = r;
}

// ---------------- per-layer neighbor-sum ----------------
__global__ __launch_bounds__(256) void k_sh_agg(int N) {
    int w = (blockIdx.x * blockDim.x + threadIdx.x) >> 5;
    int lane = threadIdx.x & 31;
    if (w >= N) return;
    int s = g_rowptr[w], e = g_rowptr[w + 1];
    float4 a0 = make_float4(0.f,0.f,0.f,0.f), a1 = a0, a2 = a0, a3 = a0;
    int i = s;
    for (; i + 3 < e; i += 4) {
        int c0 = g_cols[i], c1 = g_cols[i+1], c2 = g_cols[i+2], c3 = g_cols[i+3];
        float4 v0 = *(const float4*)&g_h[(size_t)c0 * HDIM + lane * 4];
        float4 v1 = *(const float4*)&g_h[(size_t)c1 * HDIM + lane * 4];
        float4 v2 = *(const float4*)&g_h[(size_t)c2 * HDIM + lane * 4];
        float4 v3 = *(const float4*)&g_h[(size_t)c3 * HDIM + lane * 4];
        a0.x+=v0.x; a0.y+=v0.y; a0.z+=v0.z; a0.w+=v0.w;
        a1.x+=v1.x; a1.y+=v1.y; a1.z+=v1.z; a1.w+=v1.w;
        a2.x+=v2.x; a2.y+=v2.y; a2.z+=v2.z; a2.w+=v2.w;
        a3.x+=v3.x; a3.y+=v3.y; a3.z+=v3.z; a3.w+=v3.w;
    }
    for (; i < e; i++) {
        int c = g_cols[i];
        float4 v = *(const float4*)&g_h[(size_t)c * HDIM + lane * 4];
        a0.x+=v.x; a0.y+=v.y; a0.z+=v.z; a0.w+=v.w;
    }
    float4 r;
    r.x = (a0.x + a1.x) + (a2.x + a3.x);
    r.y = (a0.y + a1.y) + (a2.y + a3.y);
    r.z = (a0.z + a1.z) + (a2.z + a3.z);
    r.w = (a0.w + a1.w) + (a2.w + a3.w);
    *(float4*)&g_sh[(size_t)w * HDIM + lane * 4] = r;
}

// ---------------- HMMA layer GEMM + fused epilogue ----------------
// D[128,128] = A[128,192] @ B^T, A=[Sh|EA] hi/lo bf16 split, D = Ah*Bh + Al*Bh + Ah*Bl
// h += relu(((D)*dinv + bc)*gamma/sqrt(1+eps) + beta)
// smem row stride 80 B (40 halves): conflict-free ldmatrix (r*20 mod 32 distinct).
#define LMM_AHI 0
#define LMM_ALO 10240
#define LMM_BHI 20480
#define LMM_BLO 30720
#define LMM_TOTAL 40960

__global__ __launch_bounds__(256, 2) void k_layer_mma(
    int l, const float* __restrict__ bcl, const float* __restrict__ gml,
    const float* __restrict__ bel, int N)
{
    extern __shared__ char smem[];
    uint32_t sb = smem_u32(smem);
    int t = threadIdx.x;
    int wid = t >> 5, lane = t & 31;
    int m0 = blockIdx.x * 128;
    int wm = wid & 3;        // warp row block: rows wm*32..+31
    int wn = wid >> 2;       // warp col block: cols wn*64..+63

    float acc[2][8][4];
#pragma unroll
    for (int a = 0; a < 2; a++)
#pragma unroll
        for (int b = 0; b < 8; b++)
#pragma unroll
            for (int c = 0; c < 4; c++) acc[a][b][c] = 0.f;

    // ldmatrix per-lane address components
    int g = lane >> 3, lr = lane & 7;
    int a_row  = (g & 1) * 8 + lr;   // A x4: m0=r0-7@k0, m1=r8-15@k0, m2=r0-7@k8, m3=r8-15@k8
    int a_koff = (g >> 1) * 8;
    int b_nrow = (g >> 1) * 8 + lr;  // B x4: m0=nt0@k0, m1=nt0@k8, m2=nt1@k0, m3=nt1@k8
    int b_koff = (g & 1) * 8;

    const __nv_bfloat16* Bh = (const __nv_bfloat16*)g_Bhi + (size_t)l * 24576;
    const __nv_bfloat16* Bl = (const __nv_bfloat16*)g_Blo + (size_t)l * 24576;

    int frow = t >> 1;               // A-fill row
    int fk0  = (t & 1) * 16;         // A-fill k base within chunk
    int bn   = t >> 1;               // B-fill row
    int bq   = t & 1;

    for (int c = 0; c < 6; c++) {
        int k0 = c * 32;
        __syncthreads();
        // ---- fill A chunk [128 rows x 32 k] hi/lo ----
        {
            bool ok = (m0 + frow) < N;
            const float* src = (k0 < HDIM)
                ? &g_sh[(size_t)(m0 + frow) * HDIM + k0 + fk0]
                : &g_ea[(size_t)(m0 + frow) * FE + (k0 - HDIM) + fk0];
#pragma unroll
            for (int i = 0; i < 4; i++) {
                float4 v = ok ? *(const float4*)(src + i * 4) : make_float4(0.f, 0.f, 0.f, 0.f);
                float rx, ry, rz, rw;
                uint32_t h01 = pack_hi2(v.x, v.y, rx, ry);
                uint32_t h23 = pack_hi2(v.z, v.w, rz, rw);
                uint32_t l01 = pack_lo2(rx, ry);
                uint32_t l23 = pack_lo2(rz, rw);
                int kq = fk0 + i * 4;
                *(uint2*)(smem + LMM_AHI + frow * 80 + kq * 2) = make_uint2(h01, h23);
                *(uint2*)(smem + LMM_ALO + frow * 80 + kq * 2) = make_uint2(l01, l23);
            }
        }
        // ---- fill B chunk [128 n x 32 k] hi/lo (pre-split, linear copy) ----
        {
#pragma unroll
            for (int i = 0; i < 2; i++) {
                int qq = bq * 2 + i;     // 0..3, 8 halves each
                uint4 vh = *(const uint4*)(Bh + (size_t)bn * 192 + k0 + qq * 8);
                uint4 vl = *(const uint4*)(Bl + (size_t)bn * 192 + k0 + qq * 8);
                *(uint4*)(smem + LMM_BHI + bn * 80 + qq * 16) = vh;
                *(uint4*)(smem + LMM_BLO + bn * 80 + qq * 16) = vl;
            }
        }
        __syncthreads();
        // ---- 2 k16 steps ----
#pragma unroll
        for (int s = 0; s < 2; s++) {
            int kl = s * 16;
            uint32_t ah[2][4], al[2][4];
#pragma unroll
            for (int mt = 0; mt < 2; mt++) {
                uint32_t aaddr = sb + LMM_AHI
                    + (uint32_t)(wm * 32 + mt * 16 + a_row) * 80
                    + (uint32_t)(kl + a_koff) * 2;
                LDSM_X4(ah[mt], aaddr);
                LDSM_X4(al[mt], aaddr + (LMM_ALO - LMM_AHI));
            }
#pragma unroll
            for (int p = 0; p < 4; p++) {
                uint32_t bh4[4], bl4[4];
                uint32_t baddr = sb + LMM_BHI
                    + (uint32_t)(wn * 64 + p * 16 + b_nrow) * 80
                    + (uint32_t)(kl + b_koff) * 2;
                LDSM_X4(bh4, baddr);
                LDSM_X4(bl4, baddr + (LMM_BLO - LMM_BHI));
#pragma unroll
                for (int h = 0; h < 2; h++) {
                    uint32_t bhp[2] = {bh4[h * 2], bh4[h * 2 + 1]};
                    uint32_t blp[2] = {bl4[h * 2], bl4[h * 2 + 1]};
                    int nt = p * 2 + h;
#pragma unroll
                    for (int mt = 0; mt < 2; mt++) {
                        MMA_BF16(acc[mt][nt], ah[mt], bhp);
                        MMA_BF16(acc[mt][nt], al[mt], bhp);
                        MMA_BF16(acc[mt][nt], ah[mt], blp);
                    }
                }
            }
        }
    }

    // ---- epilogue: fragment layout d0,d1 -> row l/4, cols (l%4)*2,+1; d2,d3 -> row+8 ----
    const float RS = rsqrtf(1.001f);
#pragma unroll
    for (int mt = 0; mt < 2; mt++) {
        int r0 = wm * 32 + mt * 16 + (lane >> 2);
#pragma unroll
        for (int hf = 0; hf < 2; hf++) {
            int r = r0 + hf * 8;
            int gm = m0 + r;
            if (gm < N) {
                float dinv = g_dinv[gm];
#pragma unroll
                for (int nt = 0; nt < 8; nt++) {
                    int col = wn * 64 + nt * 8 + (lane & 3) * 2;
                    float d0 = acc[mt][nt][hf * 2 + 0];
                    float d1 = acc[mt][nt][hf * 2 + 1];
                    float v0 = fmaf(fmaf(d0, dinv, __ldg(&bcl[col])),
                                    __ldg(&gml[col]) * RS, __ldg(&bel[col]));
                    float v1 = fmaf(fmaf(d1, dinv, __ldg(&bcl[col + 1])),
                                    __ldg(&gml[col + 1]) * RS, __ldg(&bel[col + 1]));
                    float2 old = *(float2*)&g_h[(size_t)gm * HDIM + col];
                    float2 o;
                    o.x = old.x + fmaxf(v0, 0.f);
                    o.y = old.y + fmaxf(v1, 0.f);
                    *(float2*)&g_h[(size_t)gm * HDIM + col] = o;
                }
            }
        }
    }
}

// ---------------- mean pooling per graph ----------------
__device__ __forceinline__ int lb_search(const int* a, int n, int v) {
    int lo = 0, hi = n;
    while (lo < hi) { int m = (lo + hi) >> 1; if (a[m] < v) lo = m + 1; else hi = m; }
    return lo;
}

__global__ void k_pool(const int* __restrict__ batch, int N) {
    int gid = blockIdx.x;
    int t = threadIdx.x;
    int lo = lb_search(batch, N, gid);
    int hi = lb_search(batch, N, gid + 1);
    float s = 0.f;
    for (int i = lo; i < hi; i++) s += g_h[(size_t)i * HDIM + t];
    int c = hi - lo;
    g_pool[gid * HDIM + t] = s / (c > 0 ? (float)c : 1.0f);
}

// ---------------- head ----------------
__global__ void k_head(const float* __restrict__ Wh, const float* __restrict__ bh,
                       const float* __restrict__ Wout, const float* __restrict__ bout,
                       float* __restrict__ out)
{
    __shared__ float grow[HDIM];
    __shared__ float red[HDIM];
    int gid = blockIdx.x;
    int t = threadIdx.x;
    grow[t] = g_pool[gid * HDIM + t];
    __syncthreads();
    float s = bh[t];
#pragma unroll 8
    for (int k = 0; k < HDIM; k++) s = fmaf(grow[k], Wh[k * HDIM + t], s);
    s = fmaxf(s, 0.f);
    red[t] = s * Wout[t];
    __syncthreads();
    for (int off = 64; off > 0; off >>= 1) {
        if (t < off) red[t] += red[t + off];
        __syncthreads();
    }
    if (t == 0) out[gid] = red[0] + bout[0];
}

// ---------------- launch ----------------
extern "C" void kernel_launch(void* const* d_in, const int* in_sizes, int n_in,
                              void* d_out, int out_size)
{
    const float* x      = (const float*)d_in[0];
    const int*   ei     = (const int*)  d_in[1];
    const float* eattr  = (const float*)d_in[2];
    const int*   batch  = (const int*)  d_in[3];
    const float* W_emb  = (const float*)d_in[4];
    const float* b_emb  = (const float*)d_in[5];
    const float* Wc     = (const float*)d_in[6];
    const float* bc     = (const float*)d_in[7];
    const float* gamma  = (const float*)d_in[8];
    const float* beta   = (const float*)d_in[9];
    const float* Wh     = (const float*)d_in[10];
    const float* bh     = (const float*)d_in[11];
    const float* Wout   = (const float*)d_in[12];
    const float* bout   = (const float*)d_in[13];

    int N = in_sizes[3];
    int E = in_sizes[2] / FE;
    int L = in_sizes[6] / ((HDIM + FE) * HDIM);
    if (L > MAXL) L = MAXL;
    int G = out_size;
    const int* row = ei;
    const int* col = ei + E;

    k_zero<<<(N + 255) / 256, 256>>>(N);
    k_hist<<<(E + 255) / 256, 256>>>(row, E);
    k_scan<<<1, 1024>>>(N);
    k_scatter<<<(E + 255) / 256, 256>>>(row, col, E);

    k_prepB<<<(L * 24576 + 255) / 256, 256>>>(Wc, L);
    k_embed<<<(N + 127) / 128, 256>>>(x, W_emb, b_emb, N);
    k_ea_agg<<<(N * 32 + 255) / 256, 256>>>(eattr, N);

    int gtiles = (N + 127) / 128;
    for (int l = 0; l < L; l++) {
        k_sh_agg<<<(N * 32 + 255) / 256, 256>>>(N);
        k_layer_mma<<<gtiles, 256, LMM_TOTAL>>>(
            l, bc + (size_t)l * HDIM, gamma + (size_t)l * HDIM, beta + (size_t)l * HDIM, N);
    }

    k_pool<<<G, HDIM>>>(batch, N);
    k_head<<<G, HDIM>>>(Wh, bh, Wout, bout, (float*)d_out);
}